// round 15
// baseline (speedup 1.0000x reference)
#include <cuda_runtime.h>
#include <cuda_fp16.h>
#include <cstdint>

#define BB 8
#define TT 2048
#define CC 1024
#define EE 4096
#define MM (BB*TT)      // 16384 rows
#define NCH 16
#define TSZ (TT/NCH)    // 128 rows per chunk

// ---------------- scratch (device globals; no allocations allowed) ----------
__device__ float  g_y[(size_t)MM*CC];       // rmsnorm1 output (fp32, feeds cumsum)
__device__ __half g_state[(size_t)MM*CC];   // cumulative state (fp16, A of GEMM1)
__device__ float  g_out1[(size_t)MM*CC];    // gate * x (fp32, residual + rmsnorm2 in)
__device__ __half g_h0[(size_t)MM*CC];      // rmsnorm2 output (fp16, A of GEMM2)
__device__ __half g_h[(size_t)MM*EE];       // relu MLP hidden (fp16, A of GEMM3)
__device__ float  g_csum[BB*NCH*CC];        // per-chunk column sums -> exclusive offsets
__device__ __half g_w1t[(size_t)CC*CC];     // w1^T   [N=C, K=C]  fp16
__device__ __half g_w2at[(size_t)EE*CC];    // w2a^T  [N=E, K=C]  fp16
__device__ __half g_w2bt[(size_t)CC*EE];    // w2b^T  [N=C, K=E]  fp16

// ============================ PTX helpers ====================================
__device__ __forceinline__ uint32_t smem_u32(const void* p) {
    uint32_t a;
    asm("{ .reg .u64 t; cvta.to.shared.u64 t, %1; cvt.u32.u64 %0, t; }" : "=r"(a) : "l"(p));
    return a;
}
__device__ __forceinline__ void cp16(uint32_t dst, const void* src) {
    asm volatile("cp.async.cg.shared.global [%0], [%1], 16;" :: "r"(dst), "l"(src));
}
__device__ __forceinline__ void cp_commit() {
    asm volatile("cp.async.commit_group;" ::: "memory");
}
template<int N>
__device__ __forceinline__ void cp_wait() {
    asm volatile("cp.async.wait_group %0;" :: "n"(N) : "memory");
}
__device__ __forceinline__ void ldsm4(unsigned* r, uint32_t addr) {
    asm volatile("ldmatrix.sync.aligned.m8n8.x4.shared.b16 {%0,%1,%2,%3}, [%4];"
                 : "=r"(r[0]), "=r"(r[1]), "=r"(r[2]), "=r"(r[3]) : "r"(addr));
}
// fp16 mma: D(f32) += A(f16,16x16) * B(f16,16x8)
__device__ __forceinline__ void mma16(float* d, const unsigned* a, const unsigned* b) {
    asm volatile(
        "mma.sync.aligned.m16n8k16.row.col.f32.f16.f16.f32 "
        "{%0,%1,%2,%3},{%4,%5,%6,%7},{%8,%9},{%0,%1,%2,%3};"
        : "+f"(d[0]), "+f"(d[1]), "+f"(d[2]), "+f"(d[3])
        : "r"(a[0]), "r"(a[1]), "r"(a[2]), "r"(a[3]), "r"(b[0]), "r"(b[1]));
}

// ---------------- rmsnorm: one block per row, 256 threads, float4 -----------
template<bool HALF_OUT>
__global__ __launch_bounds__(256) void rmsnorm_kernel(
    const float* __restrict__ in, const float* __restrict__ w, void* __restrict__ outv)
{
    int row = blockIdx.x;
    const float4* inr = (const float4*)(in + (size_t)row * CC);
    float4 x = inr[threadIdx.x];
    float ss = x.x*x.x + x.y*x.y + x.z*x.z + x.w*x.w;
    #pragma unroll
    for (int o = 16; o; o >>= 1) ss += __shfl_xor_sync(0xffffffffu, ss, o);
    __shared__ float s[8];
    int lane = threadIdx.x & 31, wid = threadIdx.x >> 5;
    if (lane == 0) s[wid] = ss;
    __syncthreads();
    if (wid == 0) {
        float v = (lane < 8) ? s[lane] : 0.f;
        #pragma unroll
        for (int o = 4; o; o >>= 1) v += __shfl_xor_sync(0xffffffffu, v, o);
        if (lane == 0) s[0] = v;
    }
    __syncthreads();
    float r = rsqrtf(s[0] * (1.0f / CC) + 1e-6f);
    float4 wv = ((const float4*)w)[threadIdx.x];
    float4 o4 = make_float4(x.x*r*wv.x, x.y*r*wv.y, x.z*r*wv.z, x.w*r*wv.w);
    if (HALF_OUT) {
        __half2* o = (__half2*)outv + (size_t)row * (CC/2);
        o[2*threadIdx.x    ] = __floats2half2_rn(o4.x, o4.y);
        o[2*threadIdx.x + 1] = __floats2half2_rn(o4.z, o4.w);
    } else {
        ((float4*)((float*)outv + (size_t)row * CC))[threadIdx.x] = o4;
    }
}

// ---------------- cumsum phases ---------------------------------------------
__global__ __launch_bounds__(256) void colsum_kernel() {
    int b  = blockIdx.x / NCH, ch = blockIdx.x % NCH;
    int c  = blockIdx.y * 256 + threadIdx.x;
    const float* p = g_y + ((size_t)(b*TT + ch*TSZ)) * CC + c;
    float s = 0.f;
    #pragma unroll 1
    for (int g = 0; g < TSZ; g += 8) {
        float xv[8];
        #pragma unroll
        for (int j = 0; j < 8; j++) xv[j] = p[(size_t)(g + j) * CC];
        #pragma unroll
        for (int j = 0; j < 8; j++) s += xv[j];
    }
    g_csum[(b*NCH + ch)*CC + c] = s;
}
__global__ __launch_bounds__(1024) void scan_kernel() {
    int b = blockIdx.x;
    int c = threadIdx.x;
    float run = 0.f;
    #pragma unroll
    for (int ch = 0; ch < NCH; ch++) {
        int idx = (b*NCH + ch)*CC + c;
        float v = g_csum[idx];
        g_csum[idx] = run;
        run += v;
    }
}
__global__ __launch_bounds__(256) void state_kernel() {
    int b  = blockIdx.x / NCH, ch = blockIdx.x % NCH;
    int c  = blockIdx.y * 256 + threadIdx.x;
    float run = g_csum[(b*NCH + ch)*CC + c];
    size_t base = ((size_t)(b*TT + ch*TSZ)) * CC + c;
    #pragma unroll 1
    for (int g = 0; g < TSZ; g += 8) {
        float xv[8];
        #pragma unroll
        for (int j = 0; j < 8; j++) xv[j] = g_y[base + (size_t)(g + j) * CC];
        #pragma unroll
        for (int j = 0; j < 8; j++) {
            int t = ch*TSZ + g + j;
            run += xv[j];
            float rscal = __frcp_rn(0.5f * (float)(t+1) * (float)(t+2));
            g_state[base + (size_t)(g + j) * CC] = __float2half_rn(run * rscal);
        }
    }
}

// ---------------- weight transpose (fp32 in -> fp16 out) ---------------------
__global__ __launch_bounds__(256) void transpose_kernel(
    const float* __restrict__ in, __half* __restrict__ out, int R, int Cc)
{
    __shared__ float t[32][33];
    int tx = threadIdx.x & 31, ty = threadIdx.x >> 5;   // 32x8
    int ix = blockIdx.x * 32 + tx;
    int iy = blockIdx.y * 32 + ty;
    #pragma unroll
    for (int i = 0; i < 32; i += 8)
        t[ty + i][tx] = in[(size_t)(iy + i) * Cc + ix];
    __syncthreads();
    int ox = blockIdx.y * 32 + tx;
    int oy = blockIdx.x * 32 + ty;
    #pragma unroll
    for (int i = 0; i < 32; i += 8)
        out[(size_t)(oy + i) * R + ox] = __float2half_rn(t[tx][ty + i]);
}

// ================= fp16 mma.sync GEMM, ldmatrix + cp.async 3-stage ===========
// A [M,K] K-major fp16, Bt [N,K] K-major fp16, D [M,N].
// CTA tile TM x 256 (TM=128: 8 warps as 2x4, warp tile 64x64;
//                    TM=64 : 8 warps as 1x8, warp tile 64x32) BK=64, 3 stages.
// MODE 0: D(f32) = sigmoid(acc+bias)*aux      (gate * x)
// MODE 1: D(f16) = relu(acc+bias)             (MLP hidden)
// MODE 2: D(f32) = acc + bias + aux           (out + residual)
#define BKh 64
#define PADH 72                          // halves per smem row (144B)
#define BTILEB (256*PADH*2)              // 36864 B

template<int MODE, int TM>
__global__ __launch_bounds__(256, 1) void gemm_tc(
    const __half* __restrict__ A, const __half* __restrict__ Bt,
    const float* __restrict__ bias, const float* __restrict__ aux,
    void* __restrict__ Dv, int Mdim, int Ndim, int Kdim)
{
    constexpr int WN   = (TM == 128) ? 64 : 32;   // warp tile N
    constexpr int NTP  = WN / 16;                 // B ldmatrix.x4 count (4 or 2)
    constexpr int ATILEBt = TM * PADH * 2;        // 18432 or 9216
    constexpr int STGsz   = ATILEBt + BTILEB;
    constexpr int ACH  = TM / 32;                 // A staging iters (4 or 2)

    extern __shared__ __align__(128) char smc[];
    uint32_t sb = smem_u32(smc);

    int tid  = threadIdx.x;
    int lane = tid & 31;
    int wid  = tid >> 5;
    int warp_m = (TM == 128) ? (wid >> 2) : 0;    // 0..1 or 0
    int warp_n = (TM == 128) ? (wid & 3)  : wid;  // 0..3 or 0..7
    int r = lane >> 2;       // 0..7
    int q = lane & 3;        // 0..3

    int bm = blockIdx.y * TM;
    int bn = blockIdx.x * 256;
    const __half* Ag = A  + (size_t)bm * Kdim;
    const __half* Bg = Bt + (size_t)bn * Kdim;
    int nk = Kdim / BKh;

    // per-thread ldmatrix source coordinates (within tile)
    int a_row  = warp_m * 64 + (lane & 7) + ((lane >> 3) & 1) * 8;  // + mt*16
    int a_koff = (lane >> 4) * 8;
    int b_row  = warp_n * WN + (lane & 7) + (lane >> 4) * 8;        // + ntp*16
    int b_koff = ((lane >> 3) & 1) * 8;

    // stage one ktile (A TMx64h + B 256x64h) into slot s via cp.async
    auto stage = [&](int s, int k0) {
        uint32_t da = sb + (uint32_t)s * STGsz;
        uint32_t db = da + ATILEBt;
        #pragma unroll
        for (int i = 0; i < ACH; i++) {        // A: TM*8 16B chunks
            int c   = tid + i * 256;
            int row = c >> 3;
            int ch  = c & 7;
            cp16(da + (uint32_t)row * (PADH*2) + (uint32_t)ch * 16,
                 Ag + (size_t)row * Kdim + k0 + ch * 8);
        }
        #pragma unroll
        for (int i = 0; i < 8; i++) {          // B: 2048 16B chunks
            int c   = tid + i * 256;
            int row = c >> 3;
            int ch  = c & 7;
            cp16(db + (uint32_t)row * (PADH*2) + (uint32_t)ch * 16,
                 Bg + (size_t)row * Kdim + k0 + ch * 8);
        }
        cp_commit();
    };

    float acc[4][2*NTP][4];
    #pragma unroll
    for (int i = 0; i < 4; i++)
        #pragma unroll
        for (int j = 0; j < 2*NTP; j++)
            #pragma unroll
            for (int k = 0; k < 4; k++) acc[i][j][k] = 0.f;

    stage(0, 0);
    stage(1, BKh);

    for (int kt = 0; kt < nk; kt++) {
        cp_wait<1>();
        __syncthreads();
        if (kt + 2 < nk) stage((kt + 2) % 3, (kt + 2) * BKh);
        else             cp_commit();     // keep group accounting uniform

        uint32_t sAs = sb + (uint32_t)(kt % 3) * STGsz;
        uint32_t sBs = sAs + ATILEBt;

        #pragma unroll
        for (int ks = 0; ks < 4; ks++) {           // k16 steps
            int k0s = ks * 16;
            unsigned afr[4][4];
            unsigned bfr[NTP][4];
            #pragma unroll
            for (int mt = 0; mt < 4; mt++)
                ldsm4(afr[mt], sAs + (uint32_t)((a_row + mt*16) * PADH + k0s + a_koff) * 2);
            #pragma unroll
            for (int ntp = 0; ntp < NTP; ntp++)
                ldsm4(bfr[ntp], sBs + (uint32_t)((b_row + ntp*16) * PADH + k0s + b_koff) * 2);
            #pragma unroll
            for (int mt = 0; mt < 4; mt++)
                #pragma unroll
                for (int ntp = 0; ntp < NTP; ntp++) {
                    mma16(acc[mt][2*ntp    ], afr[mt], &bfr[ntp][0]);
                    mma16(acc[mt][2*ntp + 1], afr[mt], &bfr[ntp][2]);
                }
        }
    }

    // epilogue: warp covers rows [bm+warp_m*64, +64), cols [bn+warp_n*WN, +WN)
    #pragma unroll
    for (int mt = 0; mt < 4; mt++) {
        #pragma unroll
        for (int nt = 0; nt < 2*NTP; nt++) {
            int gcol  = bn + warp_n * WN + nt * 8 + q * 2;
            float bz0 = bias[gcol], bz1 = bias[gcol + 1];
            #pragma unroll
            for (int half = 0; half < 2; half++) {
                int grow = bm + warp_m * 64 + mt * 16 + r + half * 8;
                float v0 = acc[mt][nt][half * 2 + 0] + bz0;
                float v1 = acc[mt][nt][half * 2 + 1] + bz1;
                size_t oidx = (size_t)grow * Ndim + gcol;
                if (MODE == 0) {
                    float g0 = 1.0f / (1.0f + __expf(-v0));
                    float g1 = 1.0f / (1.0f + __expf(-v1));
                    float2 xa = *(const float2*)(aux + oidx);
                    ((float2*)((float*)Dv + oidx))[0] = make_float2(g0 * xa.x, g1 * xa.y);
                } else if (MODE == 1) {
                    v0 = fmaxf(v0, 0.f);
                    v1 = fmaxf(v1, 0.f);
                    *(__half2*)((__half*)Dv + oidx) = __floats2half2_rn(v0, v1);
                } else {
                    float2 xa = *(const float2*)(aux + oidx);
                    ((float2*)((float*)Dv + oidx))[0] = make_float2(v0 + xa.x, v1 + xa.y);
                }
            }
        }
    }
}

#define GSMEM128 (3*(128*PADH*2 + BTILEB))   // 165888
#define GSMEM64  (3*(64*PADH*2  + BTILEB))   // 138240

// ---------------- launch -----------------------------------------------------
extern "C" void kernel_launch(void* const* d_in, const int* in_sizes, int n_in,
                              void* d_out, int out_size)
{
    const float* x   = (const float*)d_in[0];
    const float* n1w = (const float*)d_in[1];
    const float* w1  = (const float*)d_in[2];
    const float* b1  = (const float*)d_in[3];
    const float* n2w = (const float*)d_in[4];
    const float* w2a = (const float*)d_in[5];
    const float* b2a = (const float*)d_in[6];
    const float* w2b = (const float*)d_in[7];
    const float* b2b = (const float*)d_in[8];
    float* out = (float*)d_out;

    void *py, *pstate, *pout1, *ph0, *ph, *pw1t, *pw2at, *pw2bt;
    cudaGetSymbolAddress(&py,    g_y);
    cudaGetSymbolAddress(&pstate,g_state);
    cudaGetSymbolAddress(&pout1, g_out1);
    cudaGetSymbolAddress(&ph0,   g_h0);
    cudaGetSymbolAddress(&ph,    g_h);
    cudaGetSymbolAddress(&pw1t,  g_w1t);
    cudaGetSymbolAddress(&pw2at, g_w2at);
    cudaGetSymbolAddress(&pw2bt, g_w2bt);
    float*  y     = (float*)py;
    __half* state = (__half*)pstate;
    float*  out1  = (float*)pout1;
    __half* h0    = (__half*)ph0;
    __half* h     = (__half*)ph;
    __half* w1t   = (__half*)pw1t;
    __half* w2at  = (__half*)pw2at;
    __half* w2bt  = (__half*)pw2bt;

    static cudaStream_t s2 = nullptr;
    static cudaEvent_t evFork = nullptr, evJoin = nullptr;
    static bool init_done = false;
    if (!init_done) {
        cudaFuncSetAttribute(gemm_tc<0,64>,  cudaFuncAttributeMaxDynamicSharedMemorySize, GSMEM64);
        cudaFuncSetAttribute(gemm_tc<1,128>, cudaFuncAttributeMaxDynamicSharedMemorySize, GSMEM128);
        cudaFuncSetAttribute(gemm_tc<2,64>,  cudaFuncAttributeMaxDynamicSharedMemorySize, GSMEM64);
        cudaStreamCreateWithFlags(&s2, cudaStreamNonBlocking);
        cudaEventCreateWithFlags(&evFork, cudaEventDisableTiming);
        cudaEventCreateWithFlags(&evJoin, cudaEventDisableTiming);
        init_done = true;
    }

    // fork: weight transposes on side stream, overlapped with rmsnorm/cumsum
    cudaEventRecord(evFork, 0);
    cudaStreamWaitEvent(s2, evFork, 0);
    transpose_kernel<<<dim3(CC/32, CC/32), 256, 0, s2>>>(w1,  w1t,  CC, CC);
    transpose_kernel<<<dim3(EE/32, CC/32), 256, 0, s2>>>(w2a, w2at, CC, EE);
    transpose_kernel<<<dim3(CC/32, EE/32), 256, 0, s2>>>(w2b, w2bt, EE, CC);
    cudaEventRecord(evJoin, s2);

    // main chain
    rmsnorm_kernel<false><<<MM, 256>>>(x, n1w, y);
    colsum_kernel<<<dim3(BB*NCH, CC/256), 256>>>();
    scan_kernel<<<BB, 1024>>>();
    state_kernel<<<dim3(BB*NCH, CC/256), 256>>>();

    // join before first GEMM needs transposed weights
    cudaStreamWaitEvent(0, evJoin, 0);

    // 3) gate = sigmoid(state @ W1 + b1); out1 = gate * x   (fp32 out, TM=64)
    gemm_tc<0,64><<<dim3(CC/256, MM/64), 256, GSMEM64>>>(state, w1t, b1, x, out1, MM, CC, CC);
    // 4) rmsnorm2 (fp16 out -> A of GEMM2)
    rmsnorm_kernel<true><<<MM, 256>>>(out1, n2w, h0);
    // 5) h = relu(h0 @ W2a + b2a)   (fp16 out, TM=128)
    gemm_tc<1,128><<<dim3(EE/256, MM/128), 256, GSMEM128>>>(h0, w2at, b2a, nullptr, h, MM, EE, CC);
    // 6) out = h @ W2b + b2b + out1 (fp32 out, TM=64)
    gemm_tc<2,64><<<dim3(CC/256, MM/64), 256, GSMEM64>>>(h, w2bt, b2b, out1, out, MM, CC, EE);
}

// round 16
// speedup vs baseline: 1.0435x; 1.0435x over previous
#include <cuda_runtime.h>
#include <cuda_fp16.h>
#include <cstdint>

#define BB 8
#define TT 2048
#define CC 1024
#define EE 4096
#define MM (BB*TT)      // 16384 rows
#define NCH 16
#define TSZ (TT/NCH)    // 128 rows per chunk

// ---------------- scratch (device globals; no allocations allowed) ----------
__device__ __half g_y[(size_t)MM*CC];       // rmsnorm1 output (fp16 storage)
__device__ __half g_state[(size_t)MM*CC];   // cumulative state (fp16, A of GEMM1)
__device__ float  g_out1[(size_t)MM*CC];    // gate * x (fp32, residual + rmsnorm2 in)
__device__ __half g_h0[(size_t)MM*CC];      // rmsnorm2 output (fp16, A of GEMM2)
__device__ __half g_h[(size_t)MM*EE];       // relu MLP hidden (fp16, A of GEMM3)
__device__ float  g_csum[BB*NCH*CC];        // per-chunk column sums -> exclusive offsets
__device__ __half g_w1t[(size_t)CC*CC];     // w1^T   [N=C, K=C]  fp16
__device__ __half g_w2at[(size_t)EE*CC];    // w2a^T  [N=E, K=C]  fp16
__device__ __half g_w2bt[(size_t)CC*EE];    // w2b^T  [N=C, K=E]  fp16

// ============================ PTX helpers ====================================
__device__ __forceinline__ uint32_t smem_u32(const void* p) {
    uint32_t a;
    asm("{ .reg .u64 t; cvta.to.shared.u64 t, %1; cvt.u32.u64 %0, t; }" : "=r"(a) : "l"(p));
    return a;
}
__device__ __forceinline__ void cp16(uint32_t dst, const void* src) {
    asm volatile("cp.async.cg.shared.global [%0], [%1], 16;" :: "r"(dst), "l"(src));
}
__device__ __forceinline__ void cp_commit() {
    asm volatile("cp.async.commit_group;" ::: "memory");
}
template<int N>
__device__ __forceinline__ void cp_wait() {
    asm volatile("cp.async.wait_group %0;" :: "n"(N) : "memory");
}
__device__ __forceinline__ void ldsm4(unsigned* r, uint32_t addr) {
    asm volatile("ldmatrix.sync.aligned.m8n8.x4.shared.b16 {%0,%1,%2,%3}, [%4];"
                 : "=r"(r[0]), "=r"(r[1]), "=r"(r[2]), "=r"(r[3]) : "r"(addr));
}
// fp16 mma: D(f32) += A(f16,16x16) * B(f16,16x8)
__device__ __forceinline__ void mma16(float* d, const unsigned* a, const unsigned* b) {
    asm volatile(
        "mma.sync.aligned.m16n8k16.row.col.f32.f16.f16.f32 "
        "{%0,%1,%2,%3},{%4,%5,%6,%7},{%8,%9},{%0,%1,%2,%3};"
        : "+f"(d[0]), "+f"(d[1]), "+f"(d[2]), "+f"(d[3])
        : "r"(a[0]), "r"(a[1]), "r"(a[2]), "r"(a[3]), "r"(b[0]), "r"(b[1]));
}

// ---------------- rmsnorm: one block per row, 256 threads, float4 -----------
// fp32 in -> fp16 out
__global__ __launch_bounds__(256) void rmsnorm_kernel(
    const float* __restrict__ in, const float* __restrict__ w, __half* __restrict__ out)
{
    int row = blockIdx.x;
    const float4* inr = (const float4*)(in + (size_t)row * CC);
    float4 x = inr[threadIdx.x];
    float ss = x.x*x.x + x.y*x.y + x.z*x.z + x.w*x.w;
    #pragma unroll
    for (int o = 16; o; o >>= 1) ss += __shfl_xor_sync(0xffffffffu, ss, o);
    __shared__ float s[8];
    int lane = threadIdx.x & 31, wid = threadIdx.x >> 5;
    if (lane == 0) s[wid] = ss;
    __syncthreads();
    if (wid == 0) {
        float v = (lane < 8) ? s[lane] : 0.f;
        #pragma unroll
        for (int o = 4; o; o >>= 1) v += __shfl_xor_sync(0xffffffffu, v, o);
        if (lane == 0) s[0] = v;
    }
    __syncthreads();
    float r = rsqrtf(s[0] * (1.0f / CC) + 1e-6f);
    float4 wv = ((const float4*)w)[threadIdx.x];
    __half2* o = (__half2*)out + (size_t)row * (CC/2);
    o[2*threadIdx.x    ] = __floats2half2_rn(x.x*r*wv.x, x.y*r*wv.y);
    o[2*threadIdx.x + 1] = __floats2half2_rn(x.z*r*wv.z, x.w*r*wv.w);
}

// ---------------- cumsum phases (fp16 y storage, fp32 accumulate) ------------
__global__ __launch_bounds__(256) void colsum_kernel() {
    int b  = blockIdx.x / NCH, ch = blockIdx.x % NCH;
    int c  = blockIdx.y * 256 + threadIdx.x;
    const __half* p = g_y + ((size_t)(b*TT + ch*TSZ)) * CC + c;
    float s = 0.f;
    #pragma unroll 1
    for (int g = 0; g < TSZ; g += 8) {
        float xv[8];
        #pragma unroll
        for (int j = 0; j < 8; j++) xv[j] = __half2float(p[(size_t)(g + j) * CC]);
        #pragma unroll
        for (int j = 0; j < 8; j++) s += xv[j];
    }
    g_csum[(b*NCH + ch)*CC + c] = s;
}
__global__ __launch_bounds__(1024) void scan_kernel() {
    int b = blockIdx.x;
    int c = threadIdx.x;
    float run = 0.f;
    #pragma unroll
    for (int ch = 0; ch < NCH; ch++) {
        int idx = (b*NCH + ch)*CC + c;
        float v = g_csum[idx];
        g_csum[idx] = run;
        run += v;
    }
}
__global__ __launch_bounds__(256) void state_kernel() {
    int b  = blockIdx.x / NCH, ch = blockIdx.x % NCH;
    int c  = blockIdx.y * 256 + threadIdx.x;
    float run = g_csum[(b*NCH + ch)*CC + c];
    size_t base = ((size_t)(b*TT + ch*TSZ)) * CC + c;
    #pragma unroll 1
    for (int g = 0; g < TSZ; g += 8) {
        float xv[8];
        #pragma unroll
        for (int j = 0; j < 8; j++) xv[j] = __half2float(g_y[base + (size_t)(g + j) * CC]);
        #pragma unroll
        for (int j = 0; j < 8; j++) {
            int t = ch*TSZ + g + j;
            run += xv[j];
            float rscal = __frcp_rn(0.5f * (float)(t+1) * (float)(t+2));
            g_state[base + (size_t)(g + j) * CC] = __float2half_rn(run * rscal);
        }
    }
}

// ---------------- weight transpose (fp32 in -> fp16 out) ---------------------
__global__ __launch_bounds__(256) void transpose_kernel(
    const float* __restrict__ in, __half* __restrict__ out, int R, int Cc)
{
    __shared__ float t[32][33];
    int tx = threadIdx.x & 31, ty = threadIdx.x >> 5;   // 32x8
    int ix = blockIdx.x * 32 + tx;
    int iy = blockIdx.y * 32 + ty;
    #pragma unroll
    for (int i = 0; i < 32; i += 8)
        t[ty + i][tx] = in[(size_t)(iy + i) * Cc + ix];
    __syncthreads();
    int ox = blockIdx.y * 32 + tx;
    int oy = blockIdx.x * 32 + ty;
    #pragma unroll
    for (int i = 0; i < 32; i += 8)
        out[(size_t)(oy + i) * R + ox] = __float2half_rn(t[tx][ty + i]);
}

// ================= fp16 mma.sync GEMM, ldmatrix + cp.async 3-stage ===========
// A [M,K] K-major fp16, Bt [N,K] K-major fp16, D [M,N].
// CTA tile 128x256, warp tile 64x64 (8 warps), BK=64 halves, 3-stage ring.
// MODE 0: D(f32) = sigmoid(acc+bias)*aux      (gate * x)
// MODE 1: D(f16) = relu(acc+bias)             (MLP hidden)
// MODE 2: D(f32) = acc + bias + aux           (out + residual)
#define BKh 64
#define PADH 72                     // halves per smem row (144B)
#define ATILEB (128*PADH*2)         // 18432 B
#define BTILEB (256*PADH*2)         // 36864 B
#define STGg   (ATILEB+BTILEB)      // 55296 B per stage
#define NSTG   3
#define GSMEM  (NSTG*STGg)          // 165888 B

template<int MODE>
__global__ __launch_bounds__(256, 1) void gemm_tc(
    const __half* __restrict__ A, const __half* __restrict__ Bt,
    const float* __restrict__ bias, const float* __restrict__ aux,
    void* __restrict__ Dv, int Mdim, int Ndim, int Kdim)
{
    extern __shared__ __align__(128) char smc[];
    uint32_t sb = smem_u32(smc);

    int tid  = threadIdx.x;
    int lane = tid & 31;
    int wid  = tid >> 5;
    int warp_m = wid >> 2;   // 0..1  (64 rows each)
    int warp_n = wid & 3;    // 0..3  (64 cols each)
    int r = lane >> 2;       // 0..7
    int q = lane & 3;        // 0..3

    int bm = blockIdx.y * 128;
    int bn = blockIdx.x * 256;
    const __half* Ag = A  + (size_t)bm * Kdim;
    const __half* Bg = Bt + (size_t)bn * Kdim;
    int nk = Kdim / BKh;

    // per-thread ldmatrix source coordinates (within tile)
    int a_row  = warp_m * 64 + (lane & 7) + ((lane >> 3) & 1) * 8;  // + mt*16
    int a_koff = (lane >> 4) * 8;
    int b_row  = warp_n * 64 + (lane & 7) + (lane >> 4) * 8;        // + ntp*16
    int b_koff = ((lane >> 3) & 1) * 8;

    // stage one ktile (A 128x64h + B 256x64h) into slot s via cp.async
    auto stage = [&](int s, int k0) {
        uint32_t da = sb + (uint32_t)s * STGg;
        uint32_t db = da + ATILEB;
        #pragma unroll
        for (int i = 0; i < 4; i++) {          // A: 1024 16B chunks
            int c   = tid + i * 256;
            int row = c >> 3;
            int ch  = c & 7;
            cp16(da + (uint32_t)row * (PADH*2) + (uint32_t)ch * 16,
                 Ag + (size_t)row * Kdim + k0 + ch * 8);
        }
        #pragma unroll
        for (int i = 0; i < 8; i++) {          // B: 2048 16B chunks
            int c   = tid + i * 256;
            int row = c >> 3;
            int ch  = c & 7;
            cp16(db + (uint32_t)row * (PADH*2) + (uint32_t)ch * 16,
                 Bg + (size_t)row * Kdim + k0 + ch * 8);
        }
        cp_commit();
    };

    float acc[4][8][4];
    #pragma unroll
    for (int i = 0; i < 4; i++)
        #pragma unroll
        for (int j = 0; j < 8; j++)
            #pragma unroll
            for (int k = 0; k < 4; k++) acc[i][j][k] = 0.f;

    stage(0, 0);
    stage(1, BKh);

    for (int kt = 0; kt < nk; kt++) {
        cp_wait<1>();
        __syncthreads();
        if (kt + 2 < nk) stage((kt + 2) % NSTG, (kt + 2) * BKh);
        else             cp_commit();     // keep group accounting uniform

        uint32_t sAs = sb + (uint32_t)(kt % NSTG) * STGg;
        uint32_t sBs = sAs + ATILEB;

        #pragma unroll
        for (int ks = 0; ks < 4; ks++) {           // k16 steps
            int k0s = ks * 16;
            unsigned afr[4][4];
            unsigned bfr[4][4];
            #pragma unroll
            for (int mt = 0; mt < 4; mt++)
                ldsm4(afr[mt], sAs + (uint32_t)((a_row + mt*16) * PADH + k0s + a_koff) * 2);
            #pragma unroll
            for (int ntp = 0; ntp < 4; ntp++)
                ldsm4(bfr[ntp], sBs + (uint32_t)((b_row + ntp*16) * PADH + k0s + b_koff) * 2);
            #pragma unroll
            for (int mt = 0; mt < 4; mt++)
                #pragma unroll
                for (int ntp = 0; ntp < 4; ntp++) {
                    mma16(acc[mt][2*ntp    ], afr[mt], &bfr[ntp][0]);
                    mma16(acc[mt][2*ntp + 1], afr[mt], &bfr[ntp][2]);
                }
        }
    }

    // epilogue: warp covers rows [bm+warp_m*64, +64), cols [bn+warp_n*64, +64)
    #pragma unroll
    for (int mt = 0; mt < 4; mt++) {
        #pragma unroll
        for (int nt = 0; nt < 8; nt++) {
            int gcol  = bn + warp_n * 64 + nt * 8 + q * 2;
            float bz0 = bias[gcol], bz1 = bias[gcol + 1];
            #pragma unroll
            for (int half = 0; half < 2; half++) {
                int grow = bm + warp_m * 64 + mt * 16 + r + half * 8;
                float v0 = acc[mt][nt][half * 2 + 0] + bz0;
                float v1 = acc[mt][nt][half * 2 + 1] + bz1;
                size_t oidx = (size_t)grow * Ndim + gcol;
                if (MODE == 0) {
                    float g0 = 1.0f / (1.0f + __expf(-v0));
                    float g1 = 1.0f / (1.0f + __expf(-v1));
                    float2 xa = *(const float2*)(aux + oidx);
                    ((float2*)((float*)Dv + oidx))[0] = make_float2(g0 * xa.x, g1 * xa.y);
                } else if (MODE == 1) {
                    v0 = fmaxf(v0, 0.f);
                    v1 = fmaxf(v1, 0.f);
                    *(__half2*)((__half*)Dv + oidx) = __floats2half2_rn(v0, v1);
                } else {
                    float2 xa = *(const float2*)(aux + oidx);
                    ((float2*)((float*)Dv + oidx))[0] = make_float2(v0 + xa.x, v1 + xa.y);
                }
            }
        }
    }
}

// ---------------- launch -----------------------------------------------------
extern "C" void kernel_launch(void* const* d_in, const int* in_sizes, int n_in,
                              void* d_out, int out_size)
{
    const float* x   = (const float*)d_in[0];
    const float* n1w = (const float*)d_in[1];
    const float* w1  = (const float*)d_in[2];
    const float* b1  = (const float*)d_in[3];
    const float* n2w = (const float*)d_in[4];
    const float* w2a = (const float*)d_in[5];
    const float* b2a = (const float*)d_in[6];
    const float* w2b = (const float*)d_in[7];
    const float* b2b = (const float*)d_in[8];
    float* out = (float*)d_out;

    void *py, *pstate, *pout1, *ph0, *ph, *pw1t, *pw2at, *pw2bt;
    cudaGetSymbolAddress(&py,    g_y);
    cudaGetSymbolAddress(&pstate,g_state);
    cudaGetSymbolAddress(&pout1, g_out1);
    cudaGetSymbolAddress(&ph0,   g_h0);
    cudaGetSymbolAddress(&ph,    g_h);
    cudaGetSymbolAddress(&pw1t,  g_w1t);
    cudaGetSymbolAddress(&pw2at, g_w2at);
    cudaGetSymbolAddress(&pw2bt, g_w2bt);
    __half* y     = (__half*)py;
    __half* state = (__half*)pstate;
    float*  out1  = (float*)pout1;
    __half* h0    = (__half*)ph0;
    __half* h     = (__half*)ph;
    __half* w1t   = (__half*)pw1t;
    __half* w2at  = (__half*)pw2at;
    __half* w2bt  = (__half*)pw2bt;

    static cudaStream_t s2 = nullptr;
    static cudaEvent_t evFork = nullptr, evJoin = nullptr;
    static bool init_done = false;
    if (!init_done) {
        cudaFuncSetAttribute(gemm_tc<0>, cudaFuncAttributeMaxDynamicSharedMemorySize, GSMEM);
        cudaFuncSetAttribute(gemm_tc<1>, cudaFuncAttributeMaxDynamicSharedMemorySize, GSMEM);
        cudaFuncSetAttribute(gemm_tc<2>, cudaFuncAttributeMaxDynamicSharedMemorySize, GSMEM);
        cudaStreamCreateWithFlags(&s2, cudaStreamNonBlocking);
        cudaEventCreateWithFlags(&evFork, cudaEventDisableTiming);
        cudaEventCreateWithFlags(&evJoin, cudaEventDisableTiming);
        init_done = true;
    }

    // fork: weight transposes on side stream, overlapped with rmsnorm/cumsum
    cudaEventRecord(evFork, 0);
    cudaStreamWaitEvent(s2, evFork, 0);
    transpose_kernel<<<dim3(CC/32, CC/32), 256, 0, s2>>>(w1,  w1t,  CC, CC);
    transpose_kernel<<<dim3(EE/32, CC/32), 256, 0, s2>>>(w2a, w2at, CC, EE);
    transpose_kernel<<<dim3(CC/32, EE/32), 256, 0, s2>>>(w2b, w2bt, EE, CC);
    cudaEventRecord(evJoin, s2);

    // main chain
    rmsnorm_kernel<<<MM, 256>>>(x, n1w, y);
    colsum_kernel<<<dim3(BB*NCH, CC/256), 256>>>();
    scan_kernel<<<BB, 1024>>>();
    state_kernel<<<dim3(BB*NCH, CC/256), 256>>>();

    // join before first GEMM needs transposed weights
    cudaStreamWaitEvent(0, evJoin, 0);

    // 3) gate = sigmoid(state @ W1 + b1); out1 = gate * x   (fp32 out)
    gemm_tc<0><<<dim3(CC/256, MM/128), 256, GSMEM>>>(state, w1t, b1, x, out1, MM, CC, CC);
    // 4) rmsnorm2 (fp16 out -> A of GEMM2)
    rmsnorm_kernel<<<MM, 256>>>(out1, n2w, h0);
    // 5) h = relu(h0 @ W2a + b2a)   (fp16 out)
    gemm_tc<1><<<dim3(EE/256, MM/128), 256, GSMEM>>>(h0, w2at, b2a, nullptr, h, MM, EE, CC);
    // 6) out = h @ W2b + b2b + out1 (fp32 out)
    gemm_tc<2><<<dim3(CC/256, MM/128), 256, GSMEM>>>(h, w2bt, b2b, out1, out, MM, CC, EE);
}